// round 7
// baseline (speedup 1.0000x reference)
#include <cuda_runtime.h>

#define NMAX 100000
#define EMAX 1600000
#define EPAD (EMAX + 3 * NMAX + 16)
#define ODIM 32
#define KDIM 256
#define ALPHAF 0.2f

// ---------------- scratch (static device globals; no allocation) -------------
__device__ float  g_h[NMAX * ODIM];            // holds ALPHA * h
__device__ float  g_zA[(NMAX + 1) * ODIM];     // y ping (+ zero row at NMAX)
__device__ float  g_zB[(NMAX + 1) * ODIM];     // y pong (+ zero row at NMAX)
__device__ int    g_cnt[NMAX];
__device__ float  g_dinv[NMAX];
__device__ float  g_a1[NMAX];                  // 0.8 * dinv
__device__ int    g_ptr[NMAX + 1];             // padded CSR offsets
__device__ int    g_cursor[NMAX];
__device__ int    g_idx[EPAD];                 // source index per CSR slot
__device__ int    g_bsum[64];
__device__ int    g_boffs[64];

// ---------------- preprocessing kernels --------------------------------------

// zero cnt + the dedicated zero rows of zA/zB + prefill g_idx pad range
__global__ void init_kernel(int n, int epad) {
    int i = blockIdx.x * blockDim.x + threadIdx.x;
    if (i < n) g_cnt[i] = 0;
    if (i < ODIM) {
        g_zA[(size_t)n * ODIM + i] = 0.0f;
        g_zB[(size_t)n * ODIM + i] = 0.0f;
    }
    // prefill idx with dummy (points at zero row)
    for (int j = i; j < epad; j += gridDim.x * blockDim.x) g_idx[j] = n;
}

// edge_index is INT32 on the wire.
__global__ void count_kernel(const int* __restrict__ ei, int E) {
    int e = blockIdx.x * blockDim.x + threadIdx.x;
    if (e < E) atomicAdd(&g_cnt[ei[E + e]], 1);
}

// --- blocksum (of padded counts) + dinv fused ---
__global__ void blocksum_kernel(int n) {
    int base = blockIdx.x * 4096;
    int tid = threadIdx.x;
    int s = 0;
#pragma unroll
    for (int i = 0; i < 8; ++i) {
        int idx = base + tid * 8 + i;
        if (idx < n) {
            int c = g_cnt[idx];
            s += (c + 3) & ~3;                  // padded count
            float d = rsqrtf((float)(c + 1));   // +1 self-loop
            g_dinv[idx] = d;
            g_a1[idx] = (1.0f - ALPHAF) * d;
        }
    }
#pragma unroll
    for (int off = 16; off > 0; off >>= 1)
        s += __shfl_down_sync(0xffffffffu, s, off);
    __shared__ int wsums[16];
    int lane = tid & 31, wid = tid >> 5;
    if (lane == 0) wsums[wid] = s;
    __syncthreads();
    if (wid == 0) {
        int v = (lane < 16) ? wsums[lane] : 0;
#pragma unroll
        for (int off = 16; off > 0; off >>= 1)
            v += __shfl_down_sync(0xffffffffu, v, off);
        if (lane == 0) g_bsum[blockIdx.x] = v;
    }
}

__global__ void scan_bsums_kernel(int nb, int n) {
    int lane = threadIdx.x;
    int carry = 0;
    for (int base = 0; base < nb; base += 32) {
        int v = (base + lane < nb) ? g_bsum[base + lane] : 0;
        int inc = v;
#pragma unroll
        for (int off = 1; off < 32; off <<= 1) {
            int t = __shfl_up_sync(0xffffffffu, inc, off);
            if (lane >= off) inc += t;
        }
        if (base + lane < nb) g_boffs[base + lane] = carry + inc - v;
        carry += __shfl_sync(0xffffffffu, inc, 31);
    }
    if (lane == 0) g_ptr[n] = carry;
}

__global__ void scan_write_kernel(int n) {
    int base = blockIdx.x * 4096;
    int tid = threadIdx.x;
    int idx0 = base + tid * 8;
    int v[8], loc[8];
    int run = 0;
#pragma unroll
    for (int i = 0; i < 8; ++i) {
        int c = (idx0 + i < n) ? g_cnt[idx0 + i] : 0;
        v[i] = (c + 3) & ~3;                    // padded count
        loc[i] = run;
        run += v[i];
    }
    int lane = tid & 31, wid = tid >> 5;
    int incl = run;
#pragma unroll
    for (int off = 1; off < 32; off <<= 1) {
        int t = __shfl_up_sync(0xffffffffu, incl, off);
        if (lane >= off) incl += t;
    }
    __shared__ int wsums[16];
    if (lane == 31) wsums[wid] = incl;
    __syncthreads();
    if (wid == 0) {
        int x = (lane < 16) ? wsums[lane] : 0;
        int inc = x;
#pragma unroll
        for (int off = 1; off < 32; off <<= 1) {
            int t = __shfl_up_sync(0xffffffffu, inc, off);
            if (lane >= off) inc += t;
        }
        if (lane < 16) wsums[lane] = inc - x;  // exclusive warp offset
    }
    __syncthreads();
    int offset = g_boffs[blockIdx.x] + wsums[wid] + (incl - run);
#pragma unroll
    for (int i = 0; i < 8; ++i)
        if (idx0 + i < n) {
            g_ptr[idx0 + i] = offset + loc[i];
            g_cursor[idx0 + i] = offset + loc[i];
        }
}

__global__ void fill_kernel(const int* __restrict__ ei, int E) {
    int e = blockIdx.x * blockDim.x + threadIdx.x;
    if (e < E) {
        int r = ei[e];
        int c = ei[E + e];
        int pos = atomicAdd(&g_cursor[c], 1);
        g_idx[pos] = r;
    }
}

// ---------------- GEMM: h = x @ W^T + b; stores ALPHA*h and y0 = dinv*h ------
__global__ __launch_bounds__(128) void gemm_kernel(
    const float* __restrict__ x, const float* __restrict__ W,
    const float* __restrict__ b, int n) {
    __shared__ float4 xs4[32][18];
    __shared__ float4 ws4[32][9];
    float* xsf = (float*)xs4;   // row stride 72 floats
    float* wsf = (float*)ws4;   // row stride 36 floats
    int tid = threadIdx.x;
    int tx = tid & 15;
    int ty = tid >> 4;
    int node0 = blockIdx.x * 64;
    const float4* x4 = (const float4*)x;
    const float4* W4 = (const float4*)W;
    float acc[4][4];
#pragma unroll
    for (int m = 0; m < 4; ++m)
#pragma unroll
        for (int o = 0; o < 4; ++o) acc[m][o] = 0.0f;

    for (int kt = 0; kt < KDIM; kt += 32) {
        int kt4 = kt >> 2;
#pragma unroll
        for (int i = 0; i < 4; ++i) {
            int f = tid + i * 128;
            int row = f >> 3, kq = f & 7;
            float4 v = make_float4(0.f, 0.f, 0.f, 0.f);
            if (node0 + row < n) v = x4[(size_t)(node0 + row) * 64 + kt4 + kq];
            xsf[(kq * 4 + 0) * 72 + row] = v.x;
            xsf[(kq * 4 + 1) * 72 + row] = v.y;
            xsf[(kq * 4 + 2) * 72 + row] = v.z;
            xsf[(kq * 4 + 3) * 72 + row] = v.w;
        }
#pragma unroll
        for (int i = 0; i < 2; ++i) {
            int f = tid + i * 128;
            int j = f >> 3, kq = f & 7;
            float4 v = W4[j * 64 + kt4 + kq];
            wsf[(kq * 4 + 0) * 36 + j] = v.x;
            wsf[(kq * 4 + 1) * 36 + j] = v.y;
            wsf[(kq * 4 + 2) * 36 + j] = v.z;
            wsf[(kq * 4 + 3) * 36 + j] = v.w;
        }
        __syncthreads();
#pragma unroll
        for (int k = 0; k < 32; ++k) {
            float4 xv = xs4[k][tx];
            float4 wv = ws4[k][ty];
            float xm[4] = {xv.x, xv.y, xv.z, xv.w};
            float wm[4] = {wv.x, wv.y, wv.z, wv.w};
#pragma unroll
            for (int m = 0; m < 4; ++m)
#pragma unroll
                for (int o = 0; o < 4; ++o)
                    acc[m][o] = fmaf(xm[m], wm[o], acc[m][o]);
        }
        __syncthreads();
    }
#pragma unroll
    for (int m = 0; m < 4; ++m) {
        int node = node0 + tx * 4 + m;
        if (node < n) {
            float d = g_dinv[node];
#pragma unroll
            for (int o = 0; o < 4; ++o) {
                float hv = acc[m][o] + b[ty * 4 + o];
                g_h[(size_t)node * ODIM + ty * 4 + o] = ALPHAF * hv;  // alpha*h
                g_zA[(size_t)node * ODIM + ty * 4 + o] = d * hv;      // y0
            }
        }
    }
}

// ---------------- propagation: warp per node, 16 edges/round, padded CSR -----
__global__ __launch_bounds__(256) void prop_kernel(
    const float* __restrict__ prelu_a, float* __restrict__ out,
    int n, int it) {
    const float* yin = (it & 1) ? g_zA : g_zB;   // it=1 reads y0 in zA
    int fin = (it == 10);
    float* yout = (it & 1) ? g_zB : g_zA;

    int node = blockIdx.x * 8 + (threadIdx.x >> 5);
    if (node >= n) return;
    int lane = threadIdx.x & 31;
    int grp = lane >> 3;   // edge group 0..3
    int f4 = lane & 7;     // float4 slot within row

    int s = g_ptr[node];
    int e = g_ptr[node + 1];   // padded: (e-s) % 4 == 0
    const float4* y4 = (const float4*)yin;

    float4 acc = make_float4(0.f, 0.f, 0.f, 0.f);
    int i = s;
    for (; i + 16 <= e; i += 16) {
        int i0 = g_idx[i + grp];
        int i1 = g_idx[i + 4 + grp];
        int i2 = g_idx[i + 8 + grp];
        int i3 = g_idx[i + 12 + grp];
        float4 v0 = y4[(size_t)i0 * 8 + f4];
        float4 v1 = y4[(size_t)i1 * 8 + f4];
        float4 v2 = y4[(size_t)i2 * 8 + f4];
        float4 v3 = y4[(size_t)i3 * 8 + f4];
        acc.x += (v0.x + v1.x) + (v2.x + v3.x);
        acc.y += (v0.y + v1.y) + (v2.y + v3.y);
        acc.z += (v0.z + v1.z) + (v2.z + v3.z);
        acc.w += (v0.w + v1.w) + (v2.w + v3.w);
    }
    if (i + 8 <= e) {
        int i0 = g_idx[i + grp];
        int i1 = g_idx[i + 4 + grp];
        float4 v0 = y4[(size_t)i0 * 8 + f4];
        float4 v1 = y4[(size_t)i1 * 8 + f4];
        acc.x += v0.x + v1.x;
        acc.y += v0.y + v1.y;
        acc.z += v0.z + v1.z;
        acc.w += v0.w + v1.w;
        i += 8;
    }
    if (i + 4 <= e) {
        int i0 = g_idx[i + grp];
        float4 v0 = y4[(size_t)i0 * 8 + f4];
        acc.x += v0.x; acc.y += v0.y; acc.z += v0.z; acc.w += v0.w;
    }
    // reduce the 4 edge-groups onto lanes 0..7
    acc.x += __shfl_xor_sync(0xffffffffu, acc.x, 8);
    acc.y += __shfl_xor_sync(0xffffffffu, acc.y, 8);
    acc.z += __shfl_xor_sync(0xffffffffu, acc.z, 8);
    acc.w += __shfl_xor_sync(0xffffffffu, acc.w, 8);
    acc.x += __shfl_xor_sync(0xffffffffu, acc.x, 16);
    acc.y += __shfl_xor_sync(0xffffffffu, acc.y, 16);
    acc.z += __shfl_xor_sync(0xffffffffu, acc.z, 16);
    acc.w += __shfl_xor_sync(0xffffffffu, acc.w, 16);
    if (lane < 8) {
        float4 selfv = y4[(size_t)node * 8 + lane];    // self-loop: + y[c]
        acc.x += selfv.x; acc.y += selfv.y; acc.z += selfv.z; acc.w += selfv.w;
        float a1 = g_a1[node];
        float4 ah = ((const float4*)g_h)[(size_t)node * 8 + lane];  // alpha*h
        float4 z;
        z.x = fmaf(a1, acc.x, ah.x);
        z.y = fmaf(a1, acc.y, ah.y);
        z.z = fmaf(a1, acc.z, ah.z);
        z.w = fmaf(a1, acc.w, ah.w);
        if (fin) {
            float4 pa = ((const float4*)prelu_a)[lane];
            z.x = (z.x >= 0.f) ? z.x : pa.x * z.x;
            z.y = (z.y >= 0.f) ? z.y : pa.y * z.y;
            z.z = (z.z >= 0.f) ? z.z : pa.z * z.z;
            z.w = (z.w >= 0.f) ? z.w : pa.w * z.w;
            ((float4*)out)[(size_t)node * 8 + lane] = z;
        } else {
            float d = g_dinv[node];
            z.x *= d; z.y *= d; z.z *= d; z.w *= d;
            ((float4*)yout)[(size_t)node * 8 + lane] = z;
        }
    }
}

// ---------------- launch ------------------------------------------------------
extern "C" void kernel_launch(void* const* d_in, const int* in_sizes, int n_in,
                              void* d_out, int out_size) {
    const float* x = (const float*)d_in[0];
    const int* ei = (const int*)d_in[1];   // int32 edge_index [2, E]
    const float* W = (const float*)d_in[2];
    const float* b = (const float*)d_in[3];
    const float* pa = (const float*)d_in[4];

    int n = in_sizes[0] / KDIM;
    int E = in_sizes[1] / 2;
    int epad = E + 3 * n + 16;
    if (epad > EPAD) epad = EPAD;
    int nb = (n + 4095) / 4096;

    init_kernel<<<(n + 255) / 256, 256>>>(n, epad);          // idx 0
    count_kernel<<<(E + 255) / 256, 256>>>(ei, E);           // idx 1
    blocksum_kernel<<<nb, 512>>>(n);                         // idx 2 (dinv/a1)
    gemm_kernel<<<(n + 63) / 64, 128>>>(x, W, b, n);         // idx 3 <- profiled
    scan_bsums_kernel<<<1, 32>>>(nb, n);                     // idx 4
    scan_write_kernel<<<nb, 512>>>(n);                       // idx 5
    fill_kernel<<<(E + 255) / 256, 256>>>(ei, E);            // idx 6

    for (int it = 1; it <= 10; ++it)
        prop_kernel<<<(n + 7) / 8, 256>>>(pa, (float*)d_out, n, it);
}

// round 8
// speedup vs baseline: 1.1685x; 1.1685x over previous
#include <cuda_runtime.h>

#define NMAX 100000
#define EMAX 1600000
#define ODIM 32
#define KDIM 256
#define ALPHAF 0.2f

// ---------------- scratch (static device globals; no allocation) -------------
__device__ float  g_h[NMAX * ODIM];
__device__ float  g_zA[NMAX * ODIM];   // y ping
__device__ float  g_zB[NMAX * ODIM];   // y pong
__device__ int    g_cnt[NMAX];
__device__ float  g_dinv[NMAX];
__device__ float  g_a1[NMAX];          // 0.8 * dinv
__device__ int    g_ptr[NMAX + 1];
__device__ int    g_cursor[NMAX];
__device__ int    g_idx[EMAX + 16];    // source index per CSR slot
__device__ int    g_bsum[64];
__device__ int    g_boffs[64];

// ---------------- preprocessing kernels --------------------------------------

__global__ void zero_cnt_kernel(int n) {
    int i = blockIdx.x * blockDim.x + threadIdx.x;
    if (i < n) g_cnt[i] = 0;
}

// edge_index is INT32 on the wire.
__global__ void count_kernel(const int* __restrict__ ei, int E) {
    int e = blockIdx.x * blockDim.x + threadIdx.x;
    if (e < E) atomicAdd(&g_cnt[ei[E + e]], 1);
}

// --- blocksum + dinv fused (both read g_cnt) ---
__global__ void blocksum_kernel(int n) {
    int base = blockIdx.x * 4096;
    int tid = threadIdx.x;
    int s = 0;
#pragma unroll
    for (int i = 0; i < 8; ++i) {
        int idx = base + tid * 8 + i;
        if (idx < n) {
            int c = g_cnt[idx];
            s += c;
            float d = rsqrtf((float)(c + 1));   // +1 self-loop
            g_dinv[idx] = d;
            g_a1[idx] = (1.0f - ALPHAF) * d;
        }
    }
#pragma unroll
    for (int off = 16; off > 0; off >>= 1)
        s += __shfl_down_sync(0xffffffffu, s, off);
    __shared__ int wsums[16];
    int lane = tid & 31, wid = tid >> 5;
    if (lane == 0) wsums[wid] = s;
    __syncthreads();
    if (wid == 0) {
        int v = (lane < 16) ? wsums[lane] : 0;
#pragma unroll
        for (int off = 16; off > 0; off >>= 1)
            v += __shfl_down_sync(0xffffffffu, v, off);
        if (lane == 0) g_bsum[blockIdx.x] = v;
    }
}

__global__ void scan_bsums_kernel(int nb, int n) {
    int lane = threadIdx.x;
    int carry = 0;
    for (int base = 0; base < nb; base += 32) {
        int v = (base + lane < nb) ? g_bsum[base + lane] : 0;
        int inc = v;
#pragma unroll
        for (int off = 1; off < 32; off <<= 1) {
            int t = __shfl_up_sync(0xffffffffu, inc, off);
            if (lane >= off) inc += t;
        }
        if (base + lane < nb) g_boffs[base + lane] = carry + inc - v;
        carry += __shfl_sync(0xffffffffu, inc, 31);
    }
    if (lane == 0) g_ptr[n] = carry;
}

__global__ void scan_write_kernel(int n) {
    int base = blockIdx.x * 4096;
    int tid = threadIdx.x;
    int idx0 = base + tid * 8;
    int v[8], loc[8];
    int run = 0;
#pragma unroll
    for (int i = 0; i < 8; ++i) {
        v[i] = (idx0 + i < n) ? g_cnt[idx0 + i] : 0;
        loc[i] = run;
        run += v[i];
    }
    int lane = tid & 31, wid = tid >> 5;
    int incl = run;
#pragma unroll
    for (int off = 1; off < 32; off <<= 1) {
        int t = __shfl_up_sync(0xffffffffu, incl, off);
        if (lane >= off) incl += t;
    }
    __shared__ int wsums[16];
    if (lane == 31) wsums[wid] = incl;
    __syncthreads();
    if (wid == 0) {
        int x = (lane < 16) ? wsums[lane] : 0;
        int inc = x;
#pragma unroll
        for (int off = 1; off < 32; off <<= 1) {
            int t = __shfl_up_sync(0xffffffffu, inc, off);
            if (lane >= off) inc += t;
        }
        if (lane < 16) wsums[lane] = inc - x;  // exclusive warp offset
    }
    __syncthreads();
    int offset = g_boffs[blockIdx.x] + wsums[wid] + (incl - run);
#pragma unroll
    for (int i = 0; i < 8; ++i)
        if (idx0 + i < n) {
            g_ptr[idx0 + i] = offset + loc[i];
            g_cursor[idx0 + i] = offset + loc[i];
        }
}

__global__ void fill_kernel(const int* __restrict__ ei, int E) {
    int e = blockIdx.x * blockDim.x + threadIdx.x;
    if (e < E) {
        int r = ei[e];
        int c = ei[E + e];
        int pos = atomicAdd(&g_cursor[c], 1);
        g_idx[pos] = r;
    }
}

// ---------------- GEMM: h = x @ W^T + b; also y0 = dinv*h --------------------
// 256 threads, tile 128 nodes x 32 outs, BK=32.
// Warp-internal split: ng = lane>>3 (node group), og = lane&7 (out group) so
// BOTH shared reads are single-wavefront (xs: 4 distinct addrs broadcast x8;
// ws: 8 float4 covering a bank permutation).
__global__ __launch_bounds__(256) void gemm_kernel(
    const float* __restrict__ x, const float* __restrict__ W,
    const float* __restrict__ b, int n) {
    __shared__ float4 xs4[32][33];  // [k][node_group 0..31] +1 pad
    __shared__ float4 ws4[32][9];   // [k][out_group 0..7] +1 pad
    float* xsf = (float*)xs4;       // row stride 132 floats
    float* wsf = (float*)ws4;       // row stride 36 floats
    int tid = threadIdx.x;
    int lane = tid & 31, warp = tid >> 5;
    int ng = warp * 4 + (lane >> 3);  // node group 0..31 (4 nodes each)
    int og = lane & 7;                // out group 0..7 (4 outs each)
    int node0 = blockIdx.x * 128;
    const float4* x4 = (const float4*)x;
    const float4* W4 = (const float4*)W;
    float acc[4][4];
#pragma unroll
    for (int m = 0; m < 4; ++m)
#pragma unroll
        for (int o = 0; o < 4; ++o) acc[m][o] = 0.0f;

    for (int kt = 0; kt < KDIM; kt += 32) {
        int kt4 = kt >> 2;
        // x tile: 128 rows x 8 float4 = 1024 float4
#pragma unroll
        for (int i = 0; i < 4; ++i) {
            int f = tid + i * 256;
            int row = f >> 3, kq = f & 7;
            float4 v = make_float4(0.f, 0.f, 0.f, 0.f);
            if (node0 + row < n) v = x4[(size_t)(node0 + row) * 64 + kt4 + kq];
            xsf[(kq * 4 + 0) * 132 + row] = v.x;
            xsf[(kq * 4 + 1) * 132 + row] = v.y;
            xsf[(kq * 4 + 2) * 132 + row] = v.z;
            xsf[(kq * 4 + 3) * 132 + row] = v.w;
        }
        // W tile: 32 rows x 8 float4 = 256 float4
        {
            int row = tid >> 3, kq = tid & 7;
            float4 v = W4[row * 64 + kt4 + kq];
            wsf[(kq * 4 + 0) * 36 + row] = v.x;
            wsf[(kq * 4 + 1) * 36 + row] = v.y;
            wsf[(kq * 4 + 2) * 36 + row] = v.z;
            wsf[(kq * 4 + 3) * 36 + row] = v.w;
        }
        __syncthreads();
#pragma unroll
        for (int k = 0; k < 32; ++k) {
            float4 xv = xs4[k][ng];
            float4 wv = ws4[k][og];
            float xm[4] = {xv.x, xv.y, xv.z, xv.w};
            float wm[4] = {wv.x, wv.y, wv.z, wv.w};
#pragma unroll
            for (int m = 0; m < 4; ++m)
#pragma unroll
                for (int o = 0; o < 4; ++o)
                    acc[m][o] = fmaf(xm[m], wm[o], acc[m][o]);
        }
        __syncthreads();
    }
    float4 bv = ((const float4*)b)[og];
#pragma unroll
    for (int m = 0; m < 4; ++m) {
        int node = node0 + ng * 4 + m;
        if (node < n) {
            float d = g_dinv[node];
            float4 hv;
            hv.x = acc[m][0] + bv.x;
            hv.y = acc[m][1] + bv.y;
            hv.z = acc[m][2] + bv.z;
            hv.w = acc[m][3] + bv.w;
            ((float4*)g_h)[(size_t)node * 8 + og] = hv;
            float4 yv;
            yv.x = d * hv.x; yv.y = d * hv.y; yv.z = d * hv.z; yv.w = d * hv.w;
            ((float4*)g_zA)[(size_t)node * 8 + og] = yv;
        }
    }
}

// ---------------- propagation: warp per node, 16 edges/round -----------------
__global__ __launch_bounds__(256) void prop_kernel(
    const float* __restrict__ prelu_a, float* __restrict__ out,
    int n, int it) {
    const float* yin = (it & 1) ? g_zA : g_zB;   // it=1 reads y0 in zA
    int fin = (it == 10);
    float* yout = (it & 1) ? g_zB : g_zA;

    int node = blockIdx.x * 8 + (threadIdx.x >> 5);
    if (node >= n) return;
    int lane = threadIdx.x & 31;
    int grp = lane >> 3;   // edge group 0..3
    int f4 = lane & 7;     // float4 slot within row

    int s = g_ptr[node];
    int e = g_ptr[node + 1];
    const float4* y4 = (const float4*)yin;

    float4 acc = make_float4(0.f, 0.f, 0.f, 0.f);
    int i = s;
    for (; i + 16 <= e; i += 16) {
        int i0 = g_idx[i + grp];
        int i1 = g_idx[i + 4 + grp];
        int i2 = g_idx[i + 8 + grp];
        int i3 = g_idx[i + 12 + grp];
        float4 v0 = y4[(size_t)i0 * 8 + f4];
        float4 v1 = y4[(size_t)i1 * 8 + f4];
        float4 v2 = y4[(size_t)i2 * 8 + f4];
        float4 v3 = y4[(size_t)i3 * 8 + f4];
        acc.x += (v0.x + v1.x) + (v2.x + v3.x);
        acc.y += (v0.y + v1.y) + (v2.y + v3.y);
        acc.z += (v0.z + v1.z) + (v2.z + v3.z);
        acc.w += (v0.w + v1.w) + (v2.w + v3.w);
    }
    if (i + 8 <= e) {
        int i0 = g_idx[i + grp];
        int i1 = g_idx[i + 4 + grp];
        float4 v0 = y4[(size_t)i0 * 8 + f4];
        float4 v1 = y4[(size_t)i1 * 8 + f4];
        acc.x += v0.x + v1.x;
        acc.y += v0.y + v1.y;
        acc.z += v0.z + v1.z;
        acc.w += v0.w + v1.w;
        i += 8;
    }
    if (i + 4 <= e) {
        int i0 = g_idx[i + grp];
        float4 v0 = y4[(size_t)i0 * 8 + f4];
        acc.x += v0.x; acc.y += v0.y; acc.z += v0.z; acc.w += v0.w;
        i += 4;
    }
    // reduce the 4 edge-groups onto lanes 0..7
    acc.x += __shfl_xor_sync(0xffffffffu, acc.x, 8);
    acc.y += __shfl_xor_sync(0xffffffffu, acc.y, 8);
    acc.z += __shfl_xor_sync(0xffffffffu, acc.z, 8);
    acc.w += __shfl_xor_sync(0xffffffffu, acc.w, 8);
    acc.x += __shfl_xor_sync(0xffffffffu, acc.x, 16);
    acc.y += __shfl_xor_sync(0xffffffffu, acc.y, 16);
    acc.z += __shfl_xor_sync(0xffffffffu, acc.z, 16);
    acc.w += __shfl_xor_sync(0xffffffffu, acc.w, 16);
    // remainder (<=3 edges): lanes 0..7 gather full rows
    for (; i < e; ++i) {
        int idx = g_idx[i];
        if (lane < 8) {
            float4 v = y4[(size_t)idx * 8 + lane];
            acc.x += v.x; acc.y += v.y; acc.z += v.z; acc.w += v.w;
        }
    }
    if (lane < 8) {
        float4 selfv = y4[(size_t)node * 8 + lane];    // self-loop: + y[c]
        acc.x += selfv.x; acc.y += selfv.y; acc.z += selfv.z; acc.w += selfv.w;
        float a1 = g_a1[node];
        float4 hv = ((const float4*)g_h)[(size_t)node * 8 + lane];
        float4 z;
        z.x = fmaf(a1, acc.x, ALPHAF * hv.x);
        z.y = fmaf(a1, acc.y, ALPHAF * hv.y);
        z.z = fmaf(a1, acc.z, ALPHAF * hv.z);
        z.w = fmaf(a1, acc.w, ALPHAF * hv.w);
        if (fin) {
            float4 pa = ((const float4*)prelu_a)[lane];
            z.x = (z.x >= 0.f) ? z.x : pa.x * z.x;
            z.y = (z.y >= 0.f) ? z.y : pa.y * z.y;
            z.z = (z.z >= 0.f) ? z.z : pa.z * z.z;
            z.w = (z.w >= 0.f) ? z.w : pa.w * z.w;
            ((float4*)out)[(size_t)node * 8 + lane] = z;
        } else {
            float d = g_dinv[node];
            z.x *= d; z.y *= d; z.z *= d; z.w *= d;
            ((float4*)yout)[(size_t)node * 8 + lane] = z;
        }
    }
}

// ---------------- launch ------------------------------------------------------
extern "C" void kernel_launch(void* const* d_in, const int* in_sizes, int n_in,
                              void* d_out, int out_size) {
    const float* x = (const float*)d_in[0];
    const int* ei = (const int*)d_in[1];   // int32 edge_index [2, E]
    const float* W = (const float*)d_in[2];
    const float* b = (const float*)d_in[3];
    const float* pa = (const float*)d_in[4];

    int n = in_sizes[0] / KDIM;
    int E = in_sizes[1] / 2;
    int nb = (n + 4095) / 4096;

    zero_cnt_kernel<<<(n + 255) / 256, 256>>>(n);            // 1
    count_kernel<<<(E + 255) / 256, 256>>>(ei, E);           // 2
    blocksum_kernel<<<nb, 512>>>(n);                         // 3 (dinv/a1)
    gemm_kernel<<<(n + 127) / 128, 256>>>(x, W, b, n);       // 4 <- profiled
    scan_bsums_kernel<<<1, 32>>>(nb, n);                     // 5
    scan_write_kernel<<<nb, 512>>>(n);                       // 6
    fill_kernel<<<(E + 255) / 256, 256>>>(ei, E);            // 7

    for (int it = 1; it <= 10; ++it)
        prop_kernel<<<(n + 7) / 8, 256>>>(pa, (float*)d_out, n, it);
}

// round 9
// speedup vs baseline: 1.1736x; 1.0044x over previous
#include <cuda_runtime.h>

#define NMAX 100000
#define EMAX 1600000
#define ODIM 32
#define KDIM 256
#define ALPHAF 0.2f

// ---------------- scratch (static device globals; no allocation) -------------
__device__ float  g_h[NMAX * ODIM];
__device__ float  g_zA[NMAX * ODIM];   // y ping
__device__ float  g_zB[NMAX * ODIM];   // y pong
__device__ int    g_cnt[NMAX];
__device__ float  g_dinv[NMAX];
__device__ float  g_a1[NMAX];          // 0.8 * dinv
__device__ int    g_ptr[NMAX + 1];
__device__ int    g_cursor[NMAX];
__device__ int    g_idx[EMAX + 16];    // source index per CSR slot
__device__ int    g_bsum[64];
__device__ int    g_boffs[64];

// ---------------- preprocessing kernels --------------------------------------

__global__ void zero_cnt_kernel(int n) {
    int i = blockIdx.x * blockDim.x + threadIdx.x;
    if (i < n) g_cnt[i] = 0;
}

// edge_index is INT32 on the wire; col half starts at ei+E. 4 edges/thread.
__global__ void count_kernel(const int* __restrict__ ei, int E) {
    int i = blockIdx.x * blockDim.x + threadIdx.x;
    int Ev = E >> 2;
    if (i < Ev) {
        int4 c = ((const int4*)(ei + E))[i];
        atomicAdd(&g_cnt[c.x], 1);
        atomicAdd(&g_cnt[c.y], 1);
        atomicAdd(&g_cnt[c.z], 1);
        atomicAdd(&g_cnt[c.w], 1);
    }
    int tail = Ev * 4 + i;
    if (i < (E & 3)) atomicAdd(&g_cnt[ei[E + tail]], 1);
}

// --- blocksum + dinv fused (both read g_cnt) ---
__global__ void blocksum_kernel(int n) {
    int base = blockIdx.x * 4096;
    int tid = threadIdx.x;
    int s = 0;
#pragma unroll
    for (int i = 0; i < 8; ++i) {
        int idx = base + tid * 8 + i;
        if (idx < n) {
            int c = g_cnt[idx];
            s += c;
            float d = rsqrtf((float)(c + 1));   // +1 self-loop
            g_dinv[idx] = d;
            g_a1[idx] = (1.0f - ALPHAF) * d;
        }
    }
#pragma unroll
    for (int off = 16; off > 0; off >>= 1)
        s += __shfl_down_sync(0xffffffffu, s, off);
    __shared__ int wsums[16];
    int lane = tid & 31, wid = tid >> 5;
    if (lane == 0) wsums[wid] = s;
    __syncthreads();
    if (wid == 0) {
        int v = (lane < 16) ? wsums[lane] : 0;
#pragma unroll
        for (int off = 16; off > 0; off >>= 1)
            v += __shfl_down_sync(0xffffffffu, v, off);
        if (lane == 0) g_bsum[blockIdx.x] = v;
    }
}

__global__ void scan_bsums_kernel(int nb, int n) {
    int lane = threadIdx.x;
    int carry = 0;
    for (int base = 0; base < nb; base += 32) {
        int v = (base + lane < nb) ? g_bsum[base + lane] : 0;
        int inc = v;
#pragma unroll
        for (int off = 1; off < 32; off <<= 1) {
            int t = __shfl_up_sync(0xffffffffu, inc, off);
            if (lane >= off) inc += t;
        }
        if (base + lane < nb) g_boffs[base + lane] = carry + inc - v;
        carry += __shfl_sync(0xffffffffu, inc, 31);
    }
    if (lane == 0) g_ptr[n] = carry;
}

__global__ void scan_write_kernel(int n) {
    int base = blockIdx.x * 4096;
    int tid = threadIdx.x;
    int idx0 = base + tid * 8;
    int v[8], loc[8];
    int run = 0;
#pragma unroll
    for (int i = 0; i < 8; ++i) {
        v[i] = (idx0 + i < n) ? g_cnt[idx0 + i] : 0;
        loc[i] = run;
        run += v[i];
    }
    int lane = tid & 31, wid = tid >> 5;
    int incl = run;
#pragma unroll
    for (int off = 1; off < 32; off <<= 1) {
        int t = __shfl_up_sync(0xffffffffu, incl, off);
        if (lane >= off) incl += t;
    }
    __shared__ int wsums[16];
    if (lane == 31) wsums[wid] = incl;
    __syncthreads();
    if (wid == 0) {
        int x = (lane < 16) ? wsums[lane] : 0;
        int inc = x;
#pragma unroll
        for (int off = 1; off < 32; off <<= 1) {
            int t = __shfl_up_sync(0xffffffffu, inc, off);
            if (lane >= off) inc += t;
        }
        if (lane < 16) wsums[lane] = inc - x;  // exclusive warp offset
    }
    __syncthreads();
    int offset = g_boffs[blockIdx.x] + wsums[wid] + (incl - run);
#pragma unroll
    for (int i = 0; i < 8; ++i)
        if (idx0 + i < n) {
            g_ptr[idx0 + i] = offset + loc[i];
            g_cursor[idx0 + i] = offset + loc[i];
        }
}

__global__ void fill_kernel(const int* __restrict__ ei, int E) {
    int i = blockIdx.x * blockDim.x + threadIdx.x;
    int Ev = E >> 2;
    if (i < Ev) {
        int4 r = ((const int4*)ei)[i];
        int4 c = ((const int4*)(ei + E))[i];
        g_idx[atomicAdd(&g_cursor[c.x], 1)] = r.x;
        g_idx[atomicAdd(&g_cursor[c.y], 1)] = r.y;
        g_idx[atomicAdd(&g_cursor[c.z], 1)] = r.z;
        g_idx[atomicAdd(&g_cursor[c.w], 1)] = r.w;
    }
    int tail = Ev * 4 + i;
    if (i < (E & 3)) {
        int r = ei[tail];
        int c = ei[E + tail];
        g_idx[atomicAdd(&g_cursor[c], 1)] = r;
    }
}

// ---------------- GEMM: h = x @ W^T + b; also y0 = dinv*h --------------------
// 256 threads, tile 256 nodes x 32 outs, BK=32, 8x4 accumulators per thread.
// Per k: 3 LDS.128 feed 32 FMA.
__global__ __launch_bounds__(256) void gemm_kernel(
    const float* __restrict__ x, const float* __restrict__ W,
    const float* __restrict__ b, int n) {
    __shared__ float xsf[32 * 260];  // [k][node 0..255], row stride 260 floats
    __shared__ float wsf[32 * 36];   // [k][out 0..31],   row stride 36 floats
    int tid = threadIdx.x;
    int lane = tid & 31, warp = tid >> 5;
    int ng = warp * 4 + (lane >> 3);  // node group 0..31 (8 nodes each)
    int og = lane & 7;                // out group 0..7 (4 outs each)
    int node0 = blockIdx.x * 256;
    const float4* x4 = (const float4*)x;
    const float4* W4 = (const float4*)W;
    float acc[8][4];
#pragma unroll
    for (int m = 0; m < 8; ++m)
#pragma unroll
        for (int o = 0; o < 4; ++o) acc[m][o] = 0.0f;

    for (int kt = 0; kt < KDIM; kt += 32) {
        int kt4 = kt >> 2;
        // x tile: 256 rows x 8 float4 = 2048 float4
#pragma unroll
        for (int i = 0; i < 8; ++i) {
            int f = tid + i * 256;
            int row = f >> 3, kq = f & 7;
            float4 v = make_float4(0.f, 0.f, 0.f, 0.f);
            if (node0 + row < n) v = x4[(size_t)(node0 + row) * 64 + kt4 + kq];
            xsf[(kq * 4 + 0) * 260 + row] = v.x;
            xsf[(kq * 4 + 1) * 260 + row] = v.y;
            xsf[(kq * 4 + 2) * 260 + row] = v.z;
            xsf[(kq * 4 + 3) * 260 + row] = v.w;
        }
        // W tile: 32 rows x 8 float4 = 256 float4
        {
            int row = tid >> 3, kq = tid & 7;
            float4 v = W4[row * 64 + kt4 + kq];
            wsf[(kq * 4 + 0) * 36 + row] = v.x;
            wsf[(kq * 4 + 1) * 36 + row] = v.y;
            wsf[(kq * 4 + 2) * 36 + row] = v.z;
            wsf[(kq * 4 + 3) * 36 + row] = v.w;
        }
        __syncthreads();
#pragma unroll
        for (int k = 0; k < 32; ++k) {
            float4 xv0 = *(const float4*)&xsf[k * 260 + ng * 8];
            float4 xv1 = *(const float4*)&xsf[k * 260 + ng * 8 + 4];
            float4 wv = *(const float4*)&wsf[k * 36 + og * 4];
            float xm[8] = {xv0.x, xv0.y, xv0.z, xv0.w,
                           xv1.x, xv1.y, xv1.z, xv1.w};
            float wm[4] = {wv.x, wv.y, wv.z, wv.w};
#pragma unroll
            for (int m = 0; m < 8; ++m)
#pragma unroll
                for (int o = 0; o < 4; ++o)
                    acc[m][o] = fmaf(xm[m], wm[o], acc[m][o]);
        }
        __syncthreads();
    }
    float4 bv = ((const float4*)b)[og];
#pragma unroll
    for (int m = 0; m < 8; ++m) {
        int node = node0 + ng * 8 + m;
        if (node < n) {
            float d = g_dinv[node];
            float4 hv;
            hv.x = acc[m][0] + bv.x;
            hv.y = acc[m][1] + bv.y;
            hv.z = acc[m][2] + bv.z;
            hv.w = acc[m][3] + bv.w;
            ((float4*)g_h)[(size_t)node * 8 + og] = hv;
            float4 yv;
            yv.x = d * hv.x; yv.y = d * hv.y; yv.z = d * hv.z; yv.w = d * hv.w;
            ((float4*)g_zA)[(size_t)node * 8 + og] = yv;
        }
    }
}

// ---------------- propagation: warp per node, 16 edges/round -----------------
__global__ __launch_bounds__(256) void prop_kernel(
    const float* __restrict__ prelu_a, float* __restrict__ out,
    int n, int it) {
    const float* yin = (it & 1) ? g_zA : g_zB;   // it=1 reads y0 in zA
    int fin = (it == 10);
    float* yout = (it & 1) ? g_zB : g_zA;

    int node = blockIdx.x * 8 + (threadIdx.x >> 5);
    if (node >= n) return;
    int lane = threadIdx.x & 31;
    int grp = lane >> 3;   // edge group 0..3
    int f4 = lane & 7;     // float4 slot within row

    int s = g_ptr[node];
    int e = g_ptr[node + 1];
    const float4* y4 = (const float4*)yin;

    float4 acc = make_float4(0.f, 0.f, 0.f, 0.f);
    int i = s;
    for (; i + 16 <= e; i += 16) {
        int i0 = g_idx[i + grp];
        int i1 = g_idx[i + 4 + grp];
        int i2 = g_idx[i + 8 + grp];
        int i3 = g_idx[i + 12 + grp];
        float4 v0 = y4[(size_t)i0 * 8 + f4];
        float4 v1 = y4[(size_t)i1 * 8 + f4];
        float4 v2 = y4[(size_t)i2 * 8 + f4];
        float4 v3 = y4[(size_t)i3 * 8 + f4];
        acc.x += (v0.x + v1.x) + (v2.x + v3.x);
        acc.y += (v0.y + v1.y) + (v2.y + v3.y);
        acc.z += (v0.z + v1.z) + (v2.z + v3.z);
        acc.w += (v0.w + v1.w) + (v2.w + v3.w);
    }
    if (i + 8 <= e) {
        int i0 = g_idx[i + grp];
        int i1 = g_idx[i + 4 + grp];
        float4 v0 = y4[(size_t)i0 * 8 + f4];
        float4 v1 = y4[(size_t)i1 * 8 + f4];
        acc.x += v0.x + v1.x;
        acc.y += v0.y + v1.y;
        acc.z += v0.z + v1.z;
        acc.w += v0.w + v1.w;
        i += 8;
    }
    if (i + 4 <= e) {
        int i0 = g_idx[i + grp];
        float4 v0 = y4[(size_t)i0 * 8 + f4];
        acc.x += v0.x; acc.y += v0.y; acc.z += v0.z; acc.w += v0.w;
        i += 4;
    }
    // reduce the 4 edge-groups onto lanes 0..7
    acc.x += __shfl_xor_sync(0xffffffffu, acc.x, 8);
    acc.y += __shfl_xor_sync(0xffffffffu, acc.y, 8);
    acc.z += __shfl_xor_sync(0xffffffffu, acc.z, 8);
    acc.w += __shfl_xor_sync(0xffffffffu, acc.w, 8);
    acc.x += __shfl_xor_sync(0xffffffffu, acc.x, 16);
    acc.y += __shfl_xor_sync(0xffffffffu, acc.y, 16);
    acc.z += __shfl_xor_sync(0xffffffffu, acc.z, 16);
    acc.w += __shfl_xor_sync(0xffffffffu, acc.w, 16);
    // remainder (<=3 edges): lanes 0..7 gather full rows
    for (; i < e; ++i) {
        int idx = g_idx[i];
        if (lane < 8) {
            float4 v = y4[(size_t)idx * 8 + lane];
            acc.x += v.x; acc.y += v.y; acc.z += v.z; acc.w += v.w;
        }
    }
    if (lane < 8) {
        float4 selfv = y4[(size_t)node * 8 + lane];    // self-loop: + y[c]
        acc.x += selfv.x; acc.y += selfv.y; acc.z += selfv.z; acc.w += selfv.w;
        float a1 = g_a1[node];
        float4 hv = ((const float4*)g_h)[(size_t)node * 8 + lane];
        float4 z;
        z.x = fmaf(a1, acc.x, ALPHAF * hv.x);
        z.y = fmaf(a1, acc.y, ALPHAF * hv.y);
        z.z = fmaf(a1, acc.z, ALPHAF * hv.z);
        z.w = fmaf(a1, acc.w, ALPHAF * hv.w);
        if (fin) {
            float4 pa = ((const float4*)prelu_a)[lane];
            z.x = (z.x >= 0.f) ? z.x : pa.x * z.x;
            z.y = (z.y >= 0.f) ? z.y : pa.y * z.y;
            z.z = (z.z >= 0.f) ? z.z : pa.z * z.z;
            z.w = (z.w >= 0.f) ? z.w : pa.w * z.w;
            ((float4*)out)[(size_t)node * 8 + lane] = z;
        } else {
            float d = g_dinv[node];
            z.x *= d; z.y *= d; z.z *= d; z.w *= d;
            ((float4*)yout)[(size_t)node * 8 + lane] = z;
        }
    }
}

// ---------------- launch ------------------------------------------------------
extern "C" void kernel_launch(void* const* d_in, const int* in_sizes, int n_in,
                              void* d_out, int out_size) {
    const float* x = (const float*)d_in[0];
    const int* ei = (const int*)d_in[1];   // int32 edge_index [2, E]
    const float* W = (const float*)d_in[2];
    const float* b = (const float*)d_in[3];
    const float* pa = (const float*)d_in[4];

    int n = in_sizes[0] / KDIM;
    int E = in_sizes[1] / 2;
    int nb = (n + 4095) / 4096;
    int Ev = (E >> 2) + 4;

    zero_cnt_kernel<<<(n + 255) / 256, 256>>>(n);            // 1
    count_kernel<<<(Ev + 255) / 256, 256>>>(ei, E);          // 2
    blocksum_kernel<<<nb, 512>>>(n);                         // 3 (dinv/a1)
    gemm_kernel<<<(n + 255) / 256, 256>>>(x, W, b, n);       // 4 <- profiled
    scan_bsums_kernel<<<1, 32>>>(nb, n);                     // 5
    scan_write_kernel<<<nb, 512>>>(n);                       // 6
    fill_kernel<<<(Ev + 255) / 256, 256>>>(ei, E);           // 7

    for (int it = 1; it <= 10; ++it)
        prop_kernel<<<(n + 7) / 8, 256>>>(pa, (float*)d_out, n, it);
}

// round 10
// speedup vs baseline: 1.2190x; 1.0387x over previous
#include <cuda_runtime.h>

#define NMAX 100000
#define EMAX 1600000
#define ODIM 32
#define KDIM 256
#define ALPHAF 0.2f

// ---------------- scratch (static device globals; no allocation) -------------
__device__ float  g_h[NMAX * ODIM];
__device__ float  g_zA[NMAX * ODIM];   // y ping
__device__ float  g_zB[NMAX * ODIM];   // y pong
__device__ int    g_cnt[NMAX];
__device__ float  g_dinv[NMAX];
__device__ float  g_a1[NMAX];          // 0.8 * dinv
__device__ int    g_ptr[NMAX + 1];
__device__ int    g_cursor[NMAX];
__device__ int    g_idx[EMAX + 16];    // source index per CSR slot
__device__ int    g_bsum[64];
__device__ int    g_boffs[64];

// ---------------- preprocessing kernels --------------------------------------

__global__ void zero_cnt_kernel(int n) {
    int i = blockIdx.x * blockDim.x + threadIdx.x;
    if (i < n) g_cnt[i] = 0;
}

// edge_index is INT32 on the wire; col half starts at ei+E. 4 edges/thread.
__global__ void count_kernel(const int* __restrict__ ei, int E) {
    int i = blockIdx.x * blockDim.x + threadIdx.x;
    int Ev = E >> 2;
    if (i < Ev) {
        int4 c = ((const int4*)(ei + E))[i];
        atomicAdd(&g_cnt[c.x], 1);
        atomicAdd(&g_cnt[c.y], 1);
        atomicAdd(&g_cnt[c.z], 1);
        atomicAdd(&g_cnt[c.w], 1);
    }
    int tail = Ev * 4 + i;
    if (i < (E & 3)) atomicAdd(&g_cnt[ei[E + tail]], 1);
}

// --- blocksum + dinv fused (both read g_cnt) ---
__global__ void blocksum_kernel(int n) {
    int base = blockIdx.x * 4096;
    int tid = threadIdx.x;
    int s = 0;
#pragma unroll
    for (int i = 0; i < 8; ++i) {
        int idx = base + tid * 8 + i;
        if (idx < n) {
            int c = g_cnt[idx];
            s += c;
            float d = rsqrtf((float)(c + 1));   // +1 self-loop
            g_dinv[idx] = d;
            g_a1[idx] = (1.0f - ALPHAF) * d;
        }
    }
#pragma unroll
    for (int off = 16; off > 0; off >>= 1)
        s += __shfl_down_sync(0xffffffffu, s, off);
    __shared__ int wsums[16];
    int lane = tid & 31, wid = tid >> 5;
    if (lane == 0) wsums[wid] = s;
    __syncthreads();
    if (wid == 0) {
        int v = (lane < 16) ? wsums[lane] : 0;
#pragma unroll
        for (int off = 16; off > 0; off >>= 1)
            v += __shfl_down_sync(0xffffffffu, v, off);
        if (lane == 0) g_bsum[blockIdx.x] = v;
    }
}

__global__ void scan_bsums_kernel(int nb, int n) {
    int lane = threadIdx.x;
    int carry = 0;
    for (int base = 0; base < nb; base += 32) {
        int v = (base + lane < nb) ? g_bsum[base + lane] : 0;
        int inc = v;
#pragma unroll
        for (int off = 1; off < 32; off <<= 1) {
            int t = __shfl_up_sync(0xffffffffu, inc, off);
            if (lane >= off) inc += t;
        }
        if (base + lane < nb) g_boffs[base + lane] = carry + inc - v;
        carry += __shfl_sync(0xffffffffu, inc, 31);
    }
    if (lane == 0) g_ptr[n] = carry;
}

__global__ void scan_write_kernel(int n) {
    int base = blockIdx.x * 4096;
    int tid = threadIdx.x;
    int idx0 = base + tid * 8;
    int v[8], loc[8];
    int run = 0;
#pragma unroll
    for (int i = 0; i < 8; ++i) {
        v[i] = (idx0 + i < n) ? g_cnt[idx0 + i] : 0;
        loc[i] = run;
        run += v[i];
    }
    int lane = tid & 31, wid = tid >> 5;
    int incl = run;
#pragma unroll
    for (int off = 1; off < 32; off <<= 1) {
        int t = __shfl_up_sync(0xffffffffu, incl, off);
        if (lane >= off) incl += t;
    }
    __shared__ int wsums[16];
    if (lane == 31) wsums[wid] = incl;
    __syncthreads();
    if (wid == 0) {
        int x = (lane < 16) ? wsums[lane] : 0;
        int inc = x;
#pragma unroll
        for (int off = 1; off < 32; off <<= 1) {
            int t = __shfl_up_sync(0xffffffffu, inc, off);
            if (lane >= off) inc += t;
        }
        if (lane < 16) wsums[lane] = inc - x;  // exclusive warp offset
    }
    __syncthreads();
    int offset = g_boffs[blockIdx.x] + wsums[wid] + (incl - run);
#pragma unroll
    for (int i = 0; i < 8; ++i)
        if (idx0 + i < n) {
            g_ptr[idx0 + i] = offset + loc[i];
            g_cursor[idx0 + i] = offset + loc[i];
        }
}

__global__ void fill_kernel(const int* __restrict__ ei, int E) {
    int i = blockIdx.x * blockDim.x + threadIdx.x;
    int Ev = E >> 2;
    if (i < Ev) {
        int4 r = ((const int4*)ei)[i];
        int4 c = ((const int4*)(ei + E))[i];
        g_idx[atomicAdd(&g_cursor[c.x], 1)] = r.x;
        g_idx[atomicAdd(&g_cursor[c.y], 1)] = r.y;
        g_idx[atomicAdd(&g_cursor[c.z], 1)] = r.z;
        g_idx[atomicAdd(&g_cursor[c.w], 1)] = r.w;
    }
    int tail = Ev * 4 + i;
    if (i < (E & 3)) {
        int r = ei[tail];
        int c = ei[E + tail];
        g_idx[atomicAdd(&g_cursor[c], 1)] = r;
    }
}

// ---------------- GEMM: h = x @ W^T + b; also y0 = dinv*h --------------------
// 256 threads, tile 128 nodes x 32 outs, BK=32, 4x4 acc (R8 best shape),
// DOUBLE-BUFFERED: LDG next tile into regs before compute, STS after.
__global__ __launch_bounds__(256) void gemm_kernel(
    const float* __restrict__ x, const float* __restrict__ W,
    const float* __restrict__ b, int n) {
    __shared__ float xsf[2][32 * 132];  // [buf][k][node 0..127], stride 132
    __shared__ float wsf[2][32 * 36];   // [buf][k][out 0..31],   stride 36
    int tid = threadIdx.x;
    int lane = tid & 31, warp = tid >> 5;
    int ng = warp * 4 + (lane >> 3);  // node group 0..31 (4 nodes each)
    int og = lane & 7;                // out group 0..7 (4 outs each)
    int node0 = blockIdx.x * 128;
    const float4* x4 = (const float4*)x;
    const float4* W4 = (const float4*)W;
    float acc[4][4];
#pragma unroll
    for (int m = 0; m < 4; ++m)
#pragma unroll
        for (int o = 0; o < 4; ++o) acc[m][o] = 0.0f;

    int xrow[4], xkq[4];
#pragma unroll
    for (int i = 0; i < 4; ++i) {
        int f = tid + i * 256;
        xrow[i] = f >> 3;
        xkq[i] = f & 7;
    }
    int wrow = tid >> 3, wkq = tid & 7;

    float4 xreg[4], wreg;
    // prologue: load tile 0
#pragma unroll
    for (int i = 0; i < 4; ++i) {
        xreg[i] = make_float4(0.f, 0.f, 0.f, 0.f);
        if (node0 + xrow[i] < n)
            xreg[i] = x4[(size_t)(node0 + xrow[i]) * 64 + xkq[i]];
    }
    wreg = W4[wrow * 64 + wkq];
#pragma unroll
    for (int i = 0; i < 4; ++i) {
        xsf[0][(xkq[i] * 4 + 0) * 132 + xrow[i]] = xreg[i].x;
        xsf[0][(xkq[i] * 4 + 1) * 132 + xrow[i]] = xreg[i].y;
        xsf[0][(xkq[i] * 4 + 2) * 132 + xrow[i]] = xreg[i].z;
        xsf[0][(xkq[i] * 4 + 3) * 132 + xrow[i]] = xreg[i].w;
    }
    wsf[0][(wkq * 4 + 0) * 36 + wrow] = wreg.x;
    wsf[0][(wkq * 4 + 1) * 36 + wrow] = wreg.y;
    wsf[0][(wkq * 4 + 2) * 36 + wrow] = wreg.z;
    wsf[0][(wkq * 4 + 3) * 36 + wrow] = wreg.w;
    __syncthreads();

#pragma unroll
    for (int t = 0; t < 8; ++t) {
        int cur = t & 1;
        // issue loads for tile t+1 (overlap with compute below)
        if (t < 7) {
            int kt4 = (t + 1) * 8;
#pragma unroll
            for (int i = 0; i < 4; ++i) {
                xreg[i] = make_float4(0.f, 0.f, 0.f, 0.f);
                if (node0 + xrow[i] < n)
                    xreg[i] = x4[(size_t)(node0 + xrow[i]) * 64 + kt4 + xkq[i]];
            }
            wreg = W4[wrow * 64 + kt4 + wkq];
        }
        // compute on current buffer
        const float* xb = xsf[cur];
        const float* wb = wsf[cur];
#pragma unroll
        for (int k = 0; k < 32; ++k) {
            float4 xv = *(const float4*)&xb[k * 132 + ng * 4];
            float4 wv = *(const float4*)&wb[k * 36 + og * 4];
            float xm[4] = {xv.x, xv.y, xv.z, xv.w};
            float wm[4] = {wv.x, wv.y, wv.z, wv.w};
#pragma unroll
            for (int m = 0; m < 4; ++m)
#pragma unroll
                for (int o = 0; o < 4; ++o)
                    acc[m][o] = fmaf(xm[m], wm[o], acc[m][o]);
        }
        // store staged tile into the other buffer
        if (t < 7) {
            int nxt = cur ^ 1;
#pragma unroll
            for (int i = 0; i < 4; ++i) {
                xsf[nxt][(xkq[i] * 4 + 0) * 132 + xrow[i]] = xreg[i].x;
                xsf[nxt][(xkq[i] * 4 + 1) * 132 + xrow[i]] = xreg[i].y;
                xsf[nxt][(xkq[i] * 4 + 2) * 132 + xrow[i]] = xreg[i].z;
                xsf[nxt][(xkq[i] * 4 + 3) * 132 + xrow[i]] = xreg[i].w;
            }
            wsf[nxt][(wkq * 4 + 0) * 36 + wrow] = wreg.x;
            wsf[nxt][(wkq * 4 + 1) * 36 + wrow] = wreg.y;
            wsf[nxt][(wkq * 4 + 2) * 36 + wrow] = wreg.z;
            wsf[nxt][(wkq * 4 + 3) * 36 + wrow] = wreg.w;
        }
        __syncthreads();
    }

    float4 bv = ((const float4*)b)[og];
#pragma unroll
    for (int m = 0; m < 4; ++m) {
        int node = node0 + ng * 4 + m;
        if (node < n) {
            float d = g_dinv[node];
            float4 hv;
            hv.x = acc[m][0] + bv.x;
            hv.y = acc[m][1] + bv.y;
            hv.z = acc[m][2] + bv.z;
            hv.w = acc[m][3] + bv.w;
            ((float4*)g_h)[(size_t)node * 8 + og] = hv;
            float4 yv;
            yv.x = d * hv.x; yv.y = d * hv.y; yv.z = d * hv.z; yv.w = d * hv.w;
            ((float4*)g_zA)[(size_t)node * 8 + og] = yv;
        }
    }
}

// ---------------- propagation: warp per node, 16 edges/round -----------------
__global__ __launch_bounds__(256) void prop_kernel(
    const float* __restrict__ prelu_a, float* __restrict__ out,
    int n, int it) {
    const float* yin = (it & 1) ? g_zA : g_zB;   // it=1 reads y0 in zA
    int fin = (it == 10);
    float* yout = (it & 1) ? g_zB : g_zA;

    int node = blockIdx.x * 8 + (threadIdx.x >> 5);
    if (node >= n) return;
    int lane = threadIdx.x & 31;
    int grp = lane >> 3;   // edge group 0..3
    int f4 = lane & 7;     // float4 slot within row

    int s = g_ptr[node];
    int e = g_ptr[node + 1];
    const float4* y4 = (const float4*)yin;

    float4 acc = make_float4(0.f, 0.f, 0.f, 0.f);
    int i = s;
    for (; i + 16 <= e; i += 16) {
        int i0 = g_idx[i + grp];
        int i1 = g_idx[i + 4 + grp];
        int i2 = g_idx[i + 8 + grp];
        int i3 = g_idx[i + 12 + grp];
        float4 v0 = y4[(size_t)i0 * 8 + f4];
        float4 v1 = y4[(size_t)i1 * 8 + f4];
        float4 v2 = y4[(size_t)i2 * 8 + f4];
        float4 v3 = y4[(size_t)i3 * 8 + f4];
        acc.x += (v0.x + v1.x) + (v2.x + v3.x);
        acc.y += (v0.y + v1.y) + (v2.y + v3.y);
        acc.z += (v0.z + v1.z) + (v2.z + v3.z);
        acc.w += (v0.w + v1.w) + (v2.w + v3.w);
    }
    if (i + 8 <= e) {
        int i0 = g_idx[i + grp];
        int i1 = g_idx[i + 4 + grp];
        float4 v0 = y4[(size_t)i0 * 8 + f4];
        float4 v1 = y4[(size_t)i1 * 8 + f4];
        acc.x += v0.x + v1.x;
        acc.y += v0.y + v1.y;
        acc.z += v0.z + v1.z;
        acc.w += v0.w + v1.w;
        i += 8;
    }
    if (i + 4 <= e) {
        int i0 = g_idx[i + grp];
        float4 v0 = y4[(size_t)i0 * 8 + f4];
        acc.x += v0.x; acc.y += v0.y; acc.z += v0.z; acc.w += v0.w;
        i += 4;
    }
    // reduce the 4 edge-groups onto lanes 0..7
    acc.x += __shfl_xor_sync(0xffffffffu, acc.x, 8);
    acc.y += __shfl_xor_sync(0xffffffffu, acc.y, 8);
    acc.z += __shfl_xor_sync(0xffffffffu, acc.z, 8);
    acc.w += __shfl_xor_sync(0xffffffffu, acc.w, 8);
    acc.x += __shfl_xor_sync(0xffffffffu, acc.x, 16);
    acc.y += __shfl_xor_sync(0xffffffffu, acc.y, 16);
    acc.z += __shfl_xor_sync(0xffffffffu, acc.z, 16);
    acc.w += __shfl_xor_sync(0xffffffffu, acc.w, 16);
    // remainder (<=3 edges): lanes 0..7 gather full rows
    for (; i < e; ++i) {
        int idx = g_idx[i];
        if (lane < 8) {
            float4 v = y4[(size_t)idx * 8 + lane];
            acc.x += v.x; acc.y += v.y; acc.z += v.z; acc.w += v.w;
        }
    }
    if (lane < 8) {
        float4 selfv = y4[(size_t)node * 8 + lane];    // self-loop: + y[c]
        acc.x += selfv.x; acc.y += selfv.y; acc.z += selfv.z; acc.w += selfv.w;
        float a1 = g_a1[node];
        float4 hv = ((const float4*)g_h)[(size_t)node * 8 + lane];
        float4 z;
        z.x = fmaf(a1, acc.x, ALPHAF * hv.x);
        z.y = fmaf(a1, acc.y, ALPHAF * hv.y);
        z.z = fmaf(a1, acc.z, ALPHAF * hv.z);
        z.w = fmaf(a1, acc.w, ALPHAF * hv.w);
        if (fin) {
            float4 pa = ((const float4*)prelu_a)[lane];
            z.x = (z.x >= 0.f) ? z.x : pa.x * z.x;
            z.y = (z.y >= 0.f) ? z.y : pa.y * z.y;
            z.z = (z.z >= 0.f) ? z.z : pa.z * z.z;
            z.w = (z.w >= 0.f) ? z.w : pa.w * z.w;
            ((float4*)out)[(size_t)node * 8 + lane] = z;
        } else {
            float d = g_dinv[node];
            z.x *= d; z.y *= d; z.z *= d; z.w *= d;
            ((float4*)yout)[(size_t)node * 8 + lane] = z;
        }
    }
}

// ---------------- launch ------------------------------------------------------
extern "C" void kernel_launch(void* const* d_in, const int* in_sizes, int n_in,
                              void* d_out, int out_size) {
    const float* x = (const float*)d_in[0];
    const int* ei = (const int*)d_in[1];   // int32 edge_index [2, E]
    const float* W = (const float*)d_in[2];
    const float* b = (const float*)d_in[3];
    const float* pa = (const float*)d_in[4];

    int n = in_sizes[0] / KDIM;
    int E = in_sizes[1] / 2;
    int nb = (n + 4095) / 4096;
    int Ev = (E >> 2) + 4;

    zero_cnt_kernel<<<(n + 255) / 256, 256>>>(n);            // 1
    count_kernel<<<(Ev + 255) / 256, 256>>>(ei, E);          // 2
    blocksum_kernel<<<nb, 512>>>(n);                         // 3 (dinv/a1)
    gemm_kernel<<<(n + 127) / 128, 256>>>(x, W, b, n);       // 4 <- profiled
    scan_bsums_kernel<<<1, 32>>>(nb, n);                     // 5
    scan_write_kernel<<<nb, 512>>>(n);                       // 6
    fill_kernel<<<(Ev + 255) / 256, 256>>>(ei, E);           // 7

    for (int it = 1; it <= 10; ++it)
        prop_kernel<<<(n + 7) / 8, 256>>>(pa, (float*)d_out, n, it);
}